// round 4
// baseline (speedup 1.0000x reference)
#include <cuda_runtime.h>
#include <cuda_fp16.h>
#include <cuda_bf16.h>
#include <math.h>

// Problem constants
#define T_DIM 512
#define B_DIM 256
#define E_DIM 256
#define H_DIM 256
#define G3    768   // 3*H

// Recurrence W layout: chunks (groups of 4 k-values) 0..KQ_SMEM-1 are fp32 and
// cached in shared memory; chunks KQ_SMEM..63 stream from L2 as fp16.
#define KQ_SMEM   18
#define KQ_STREAM (64 - KQ_SMEM)        // 46
// smem: double-buffered h (2*256*float2 = 4KB) + fp32 W cache (3*18*256*16B = 216KB)
#define SMEM_REC (4096 + 3 * KQ_SMEM * 256 * 16)

// ---------------------------------------------------------------------------
// Scratch (static __device__ globals — the sanctioned no-alloc workaround)
// ---------------------------------------------------------------------------
__device__ float  g_gi[(size_t)T_DIM * B_DIM * G3];   // gi[t][b][3H], ~403 MB
__device__ float4 g_wp [3 * KQ_SMEM   * 256];         // fp32 W chunks for smem cache
__device__ uint2  g_wph[3 * KQ_STREAM * 256];         // fp16 W chunks (half2 x2) for L2 stream
__device__ float  g_hfin[B_DIM * H_DIM];              // final hidden states

// ---------------------------------------------------------------------------
// K1: pack/transpose W_hh. For chunk kq (4 k-values) of gate g, output unit i:
//   kq <  KQ_SMEM : g_wp [(g*KQ_SMEM+kq)*256 + i]          = fp32x4
//   kq >= KQ_SMEM : g_wph[(g*KQ_STREAM+(kq-KQ_SMEM))*256+i] = half2x2
// ---------------------------------------------------------------------------
__global__ void pack_whh_kernel(const float* __restrict__ whh) {
    int idx = blockIdx.x * 256 + threadIdx.x;   // 0 .. 49151
    int i   = idx & 255;                        // hidden output index
    int gkq = idx >> 8;                         // g*64 + kq
    int g   = gkq >> 6;
    int kq  = gkq & 63;
    const float* src = whh + ((size_t)(g * 256 + i)) * 256 + 4 * kq;
    float s0 = src[0], s1 = src[1], s2 = src[2], s3 = src[3];
    if (kq < KQ_SMEM) {
        g_wp[(g * KQ_SMEM + kq) * 256 + i] = make_float4(s0, s1, s2, s3);
    } else {
        __half2 h01 = __floats2half2_rn(s0, s1);
        __half2 h23 = __floats2half2_rn(s2, s3);
        uint2 u;
        u.x = *reinterpret_cast<unsigned*>(&h01);
        u.y = *reinterpret_cast<unsigned*>(&h23);
        g_wph[(g * KQ_STREAM + (kq - KQ_SMEM)) * 256 + i] = u;
    }
}

// ---------------------------------------------------------------------------
// K2: gi = x @ W_ih^T + b_ih for all (t,b). 64x64 tile, BK=16, 256 threads,
// 4x4 micro-tile. Tiles whose 64-row batch range is fully inactive at their
// timestep are skipped (lengths sorted descending -> prefix of actives).
// ---------------------------------------------------------------------------
__global__ void __launch_bounds__(256) gi_gemm_kernel(
    const float* __restrict__ x, const float* __restrict__ wih,
    const float* __restrict__ bih, const int* __restrict__ lengths)
{
    __shared__ __align__(16) float As[16][64];
    __shared__ __align__(16) float Bs[16][64];
    __shared__ int s_nact;

    int tileN = blockIdx.x;             // 0..11  (j tile)
    int row0  = blockIdx.y << 6;        // flattened row = t*256 + b
    int t     = row0 >> 8;              // 64 rows share one t (256 % 64 == 0)
    int b0    = row0 & 255;

    if (threadIdx.x == 0) {
        int lo = 0, hi = B_DIM;
        while (lo < hi) {
            int mid = (lo + hi) >> 1;
            if (lengths[mid] > t) lo = mid + 1; else hi = mid;
        }
        s_nact = lo;
    }
    __syncthreads();
    if (b0 >= s_nact) return;           // whole tile inactive at this t

    int tid = threadIdx.x;
    int tx  = tid & 15;
    int ty  = tid >> 4;

    float c[4][4];
#pragma unroll
    for (int i = 0; i < 4; i++)
#pragma unroll
        for (int j = 0; j < 4; j++) c[i][j] = 0.f;

    int j0 = tileN << 6;
    int lr = tid >> 2;
    int lk = (tid & 3) << 2;
    const float* Ag = x   + (size_t)(row0 + lr) * 256 + lk;
    const float* Bg = wih + (size_t)(j0   + lr) * 256 + lk;

    for (int kk = 0; kk < 256; kk += 16) {
        float4 av = *reinterpret_cast<const float4*>(Ag + kk);
        float4 bv = *reinterpret_cast<const float4*>(Bg + kk);
        __syncthreads();
        As[lk + 0][lr] = av.x; As[lk + 1][lr] = av.y;
        As[lk + 2][lr] = av.z; As[lk + 3][lr] = av.w;
        Bs[lk + 0][lr] = bv.x; Bs[lk + 1][lr] = bv.y;
        Bs[lk + 2][lr] = bv.z; Bs[lk + 3][lr] = bv.w;
        __syncthreads();
#pragma unroll
        for (int k = 0; k < 16; k++) {
            float4 a = *reinterpret_cast<const float4*>(&As[k][ty << 2]);
            float4 b = *reinterpret_cast<const float4*>(&Bs[k][tx << 2]);
            c[0][0] += a.x * b.x; c[0][1] += a.x * b.y; c[0][2] += a.x * b.z; c[0][3] += a.x * b.w;
            c[1][0] += a.y * b.x; c[1][1] += a.y * b.y; c[1][2] += a.y * b.z; c[1][3] += a.y * b.w;
            c[2][0] += a.z * b.x; c[2][1] += a.z * b.y; c[2][2] += a.z * b.z; c[2][3] += a.z * b.w;
            c[3][0] += a.w * b.x; c[3][1] += a.w * b.y; c[3][2] += a.w * b.z; c[3][3] += a.w * b.w;
        }
    }

    float4 bb = *reinterpret_cast<const float4*>(&bih[j0 + (tx << 2)]);
#pragma unroll
    for (int i = 0; i < 4; i++) {
        float4 o = make_float4(c[i][0] + bb.x, c[i][1] + bb.y,
                               c[i][2] + bb.z, c[i][3] + bb.w);
        *reinterpret_cast<float4*>(
            &g_gi[(size_t)(row0 + (ty << 2) + i) * G3 + j0 + (tx << 2)]) = o;
    }
}

// ---------------------------------------------------------------------------
// K3: persistent recurrence. 128 CTAs x 2 adjacent batch rows, 256 threads =
// one hidden unit each. W: KQ_SMEM fp32 chunks from smem + KQ_STREAM fp16
// chunks from L2. h double-buffered in smem (ONE barrier/step). gi[t]
// prefetched before the matvec so its latency hides under the FFMA stream.
// ---------------------------------------------------------------------------
__device__ __forceinline__ float fast_sigm(float v) {
    return __fdividef(1.0f, 1.0f + __expf(-v));
}
__device__ __forceinline__ float fast_tanh(float v) {
    float e = __expf(2.0f * v);
    return __fdividef(e - 1.0f, e + 1.0f);
}

__global__ void __launch_bounds__(256) gru_rec_kernel(
    const int* __restrict__ lengths, const float* __restrict__ bhh)
{
    extern __shared__ __align__(16) char dsm[];
    float2* hbuf = reinterpret_cast<float2*>(dsm);            // [2][256] float2
    float4* ws   = reinterpret_cast<float4*>(dsm + 4096);     // [3][KQ_SMEM][256]

    int pair = blockIdx.x;              // 0..127
    int bA = pair * 2, bB = pair * 2 + 1;
    int lenA = lengths[bA], lenB = lengths[bB];
    int lmax = max(lenA, lenB);
    int tid  = threadIdx.x;

    // Cooperative load of the fp32 smem-resident W slice
    for (int i = tid; i < 3 * KQ_SMEM * 256; i += 256)
        ws[i] = g_wp[i];
    hbuf[tid]       = make_float2(0.f, 0.f);
    hbuf[256 + tid] = make_float2(0.f, 0.f);

    float bhr = bhh[tid], bhz = bhh[256 + tid], bhn = bhh[512 + tid];
    const float* giA = g_gi + (size_t)bA * G3 + tid;
    const float* giB = g_gi + (size_t)bB * G3 + tid;
    __syncthreads();

    int p = 0;
    for (int t = 0; t < lmax; t++) {
        // ---- prefetch gi[t] (latency hides under the matvec) ----
        size_t toff = (size_t)t * (B_DIM * G3);
        bool actA = t < lenA, actB = t < lenB;
        float irA = 0.f, izA = 0.f, inA = 0.f;
        float irB = 0.f, izB = 0.f, inB = 0.f;
        if (actA) { irA = giA[toff]; izA = giA[toff + 256]; inA = giA[toff + 512]; }
        if (actB) { irB = giB[toff]; izB = giB[toff + 256]; inB = giB[toff + 512]; }

        float ar0 = 0.f, az0 = 0.f, an0 = 0.f;
        float ar1 = 0.f, az1 = 0.f, an1 = 0.f;
        const float4* hp = reinterpret_cast<const float4*>(hbuf + 256 * p);

        // ---- fp32 smem-resident chunk of W ----
#pragma unroll 6
        for (int kq = 0; kq < KQ_SMEM; kq++) {
            float4 p01 = hp[2 * kq];
            float4 p23 = hp[2 * kq + 1];
            float4 wr = ws[(0 * KQ_SMEM + kq) * 256 + tid];
            float4 wz = ws[(1 * KQ_SMEM + kq) * 256 + tid];
            float4 wn = ws[(2 * KQ_SMEM + kq) * 256 + tid];
            ar0 += wr.x * p01.x + wr.y * p01.z + wr.z * p23.x + wr.w * p23.z;
            az0 += wz.x * p01.x + wz.y * p01.z + wz.z * p23.x + wz.w * p23.z;
            an0 += wn.x * p01.x + wn.y * p01.z + wn.z * p23.x + wn.w * p23.z;
            ar1 += wr.x * p01.y + wr.y * p01.w + wr.z * p23.y + wr.w * p23.w;
            az1 += wz.x * p01.y + wz.y * p01.w + wz.z * p23.y + wz.w * p23.w;
            an1 += wn.x * p01.y + wn.y * p01.w + wn.z * p23.y + wn.w * p23.w;
        }
        // ---- fp16 L2-streamed remainder of W ----
#pragma unroll 4
        for (int kqs = 0; kqs < KQ_STREAM; kqs++) {
            int kq = KQ_SMEM + kqs;
            float4 p01 = hp[2 * kq];
            float4 p23 = hp[2 * kq + 1];
            uint2 ur = g_wph[(0 * KQ_STREAM + kqs) * 256 + tid];
            uint2 uz = g_wph[(1 * KQ_STREAM + kqs) * 256 + tid];
            uint2 un = g_wph[(2 * KQ_STREAM + kqs) * 256 + tid];
            float2 rlo = __half22float2(*reinterpret_cast<__half2*>(&ur.x));
            float2 rhi = __half22float2(*reinterpret_cast<__half2*>(&ur.y));
            float2 zlo = __half22float2(*reinterpret_cast<__half2*>(&uz.x));
            float2 zhi = __half22float2(*reinterpret_cast<__half2*>(&uz.y));
            float2 nlo = __half22float2(*reinterpret_cast<__half2*>(&un.x));
            float2 nhi = __half22float2(*reinterpret_cast<__half2*>(&un.y));
            ar0 += rlo.x * p01.x + rlo.y * p01.z + rhi.x * p23.x + rhi.y * p23.z;
            az0 += zlo.x * p01.x + zlo.y * p01.z + zhi.x * p23.x + zhi.y * p23.z;
            an0 += nlo.x * p01.x + nlo.y * p01.z + nhi.x * p23.x + nhi.y * p23.z;
            ar1 += rlo.x * p01.y + rlo.y * p01.w + rhi.x * p23.y + rhi.y * p23.w;
            az1 += zlo.x * p01.y + zlo.y * p01.w + zhi.x * p23.y + zhi.y * p23.w;
            an1 += nlo.x * p01.y + nlo.y * p01.w + nhi.x * p23.y + nhi.y * p23.w;
        }

        float2 hold = hbuf[256 * p + tid];
        float hA = hold.x, hB = hold.y;

        if (actA) {
            float r = fast_sigm(irA + ar0 + bhr);
            float z = fast_sigm(izA + az0 + bhz);
            float n = fast_tanh(inA + r * (an0 + bhn));
            hA = (1.f - z) * n + z * hA;
        }
        if (actB) {
            float r = fast_sigm(irB + ar1 + bhr);
            float z = fast_sigm(izB + az1 + bhz);
            float n = fast_tanh(inB + r * (an1 + bhn));
            hB = (1.f - z) * n + z * hB;
        }

        hbuf[256 * (p ^ 1) + tid] = make_float2(hA, hB);
        __syncthreads();                 // single barrier: publish h(t+1)
        p ^= 1;
    }

    float2 hf = hbuf[256 * p + tid];
    g_hfin[bA * 256 + tid] = hf.x;
    g_hfin[bB * 256 + tid] = hf.y;
}

// ---------------------------------------------------------------------------
// K4: out[i, :] = h_final[unsorted_indices[i], :]   (output is [1, B, H] fp32)
// ---------------------------------------------------------------------------
__global__ void gather_kernel(const int* __restrict__ u, float* __restrict__ out) {
    int b = blockIdx.x;
    out[b * 256 + threadIdx.x] = g_hfin[(size_t)u[b] * 256 + threadIdx.x];
}

// ---------------------------------------------------------------------------
// Launch. Inputs (metadata order): x, W_ih, W_hh, b_ih, b_hh, lengths,
// unsorted_indices. All launches graph-capturable; no sync, no alloc.
// ---------------------------------------------------------------------------
extern "C" void kernel_launch(void* const* d_in, const int* in_sizes, int n_in,
                              void* d_out, int out_size)
{
    const float* x       = (const float*)d_in[0];
    const float* wih     = (const float*)d_in[1];
    const float* whh     = (const float*)d_in[2];
    const float* bih     = (const float*)d_in[3];
    const float* bhh     = (const float*)d_in[4];
    const int*   lengths = (const int*)d_in[5];
    const int*   uns     = (const int*)d_in[6];
    float* out = (float*)d_out;

    static int smem_set = 0;
    if (!smem_set) {
        cudaFuncSetAttribute(gru_rec_kernel,
                             cudaFuncAttributeMaxDynamicSharedMemorySize,
                             SMEM_REC);
        smem_set = 1;
    }

    pack_whh_kernel<<<192, 256>>>(whh);

    dim3 g2(G3 / 64, (T_DIM * B_DIM) / 64);   // (12, 2048)
    gi_gemm_kernel<<<g2, 256>>>(x, wih, bih, lengths);

    gru_rec_kernel<<<B_DIM / 2, 256, SMEM_REC>>>(lengths, bhh);

    gather_kernel<<<B_DIM, 256>>>(uns, out);
}

// round 12
// speedup vs baseline: 1.1730x; 1.1730x over previous
#include <cuda_runtime.h>
#include <cuda_fp16.h>
#include <cuda_bf16.h>
#include <math.h>

// Problem constants
#define T_DIM 512
#define B_DIM 256
#define E_DIM 256
#define H_DIM 256
#define G3    768   // 3*H

// Recurrence W: all fp16, packed [gate][kq][unit] (kq = group of 4 k-values).
// Chunks 0..KQ_SMEM-1 cached in shared memory; rest streamed from L2.
#define KQ_SMEM 34
// smem: double-buffered h (2*256*float2 = 4KB) + fp16 W cache (3*34*256*8B)
#define SMEM_REC (4096 + 3 * KQ_SMEM * 256 * 8)   // 212992

// ---------------------------------------------------------------------------
// Scratch (static __device__ globals — the sanctioned no-alloc workaround)
// ---------------------------------------------------------------------------
__device__ float g_gi[(size_t)T_DIM * B_DIM * G3];   // gi[t][b][3H], ~403 MB
__device__ uint2 g_wph[3 * 64 * 256];                // fp16 W_hh: half2 x2 per 4 k
__device__ float g_hfin[B_DIM * H_DIM];              // final hidden states

// ---------------------------------------------------------------------------
// K1: pack/transpose W_hh to fp16. For chunk kq of gate g, output unit i:
//   g_wph[(g*64+kq)*256 + i] = {h2(W[g*256+i][4kq],W[..][4kq+1]), h2(..+2,..+3)}
// ---------------------------------------------------------------------------
__global__ void __launch_bounds__(256) pack_whh_kernel(const float* __restrict__ whh) {
    int idx = blockIdx.x * 256 + threadIdx.x;   // 0 .. 49151
    int i   = idx & 255;
    int gkq = idx >> 8;
    int g   = gkq >> 6;
    int kq  = gkq & 63;
    const float* src = whh + ((size_t)(g * 256 + i)) * 256 + 4 * kq;
    __half2 h01 = __floats2half2_rn(src[0], src[1]);
    __half2 h23 = __floats2half2_rn(src[2], src[3]);
    uint2 u;
    u.x = *reinterpret_cast<unsigned*>(&h01);
    u.y = *reinterpret_cast<unsigned*>(&h23);
    g_wph[idx] = u;
}

// ---------------------------------------------------------------------------
// K2: gi = x @ W_ih^T + b_ih. 64x64 tile, BK=16, 256 threads, 4x4 micro-tile.
// Pipelined: next chunk's LDG issued right after STS-sync so its latency
// hides under the 16-k FFMA block. Inactive 64-row tiles skipped.
// ---------------------------------------------------------------------------
__global__ void __launch_bounds__(256) gi_gemm_kernel(
    const float* __restrict__ x, const float* __restrict__ wih,
    const float* __restrict__ bih, const int* __restrict__ lengths)
{
    __shared__ __align__(16) float As[16][64];
    __shared__ __align__(16) float Bs[16][64];
    __shared__ int s_nact;

    int tileN = blockIdx.x;             // 0..11  (j tile)
    int row0  = blockIdx.y << 6;        // flattened row = t*256 + b
    int t     = row0 >> 8;              // 64 rows share one t (256 % 64 == 0)
    int b0    = row0 & 255;

    if (threadIdx.x == 0) {
        int lo = 0, hi = B_DIM;
        while (lo < hi) {
            int mid = (lo + hi) >> 1;
            if (lengths[mid] > t) lo = mid + 1; else hi = mid;
        }
        s_nact = lo;
    }
    __syncthreads();
    if (b0 >= s_nact) return;           // whole tile inactive at this t

    int tid = threadIdx.x;
    int tx  = tid & 15;
    int ty  = tid >> 4;

    float c[4][4];
#pragma unroll
    for (int i = 0; i < 4; i++)
#pragma unroll
        for (int j = 0; j < 4; j++) c[i][j] = 0.f;

    int j0 = tileN << 6;
    int lr = tid >> 2;                  // 0..63: row within tile
    int lk = (tid & 3) << 2;            // 0,4,8,12: k offset within chunk
    const float* Ag = x   + (size_t)(row0 + lr) * 256 + lk;
    const float* Bg = wih + (size_t)(j0   + lr) * 256 + lk;

    // prologue: chunk 0 in registers
    float4 av = *reinterpret_cast<const float4*>(Ag);
    float4 bv = *reinterpret_cast<const float4*>(Bg);

    for (int kk = 0; kk < 256; kk += 16) {
        __syncthreads();                // previous compute done reading smem
        As[lk + 0][lr] = av.x; As[lk + 1][lr] = av.y;
        As[lk + 2][lr] = av.z; As[lk + 3][lr] = av.w;
        Bs[lk + 0][lr] = bv.x; Bs[lk + 1][lr] = bv.y;
        Bs[lk + 2][lr] = bv.z; Bs[lk + 3][lr] = bv.w;
        __syncthreads();
        if (kk + 16 < 256) {            // prefetch next chunk (hides under FMA)
            av = *reinterpret_cast<const float4*>(Ag + kk + 16);
            bv = *reinterpret_cast<const float4*>(Bg + kk + 16);
        }
#pragma unroll
        for (int k = 0; k < 16; k++) {
            float4 a = *reinterpret_cast<const float4*>(&As[k][ty << 2]);
            float4 b = *reinterpret_cast<const float4*>(&Bs[k][tx << 2]);
            c[0][0] += a.x * b.x; c[0][1] += a.x * b.y; c[0][2] += a.x * b.z; c[0][3] += a.x * b.w;
            c[1][0] += a.y * b.x; c[1][1] += a.y * b.y; c[1][2] += a.y * b.z; c[1][3] += a.y * b.w;
            c[2][0] += a.z * b.x; c[2][1] += a.z * b.y; c[2][2] += a.z * b.z; c[2][3] += a.z * b.w;
            c[3][0] += a.w * b.x; c[3][1] += a.w * b.y; c[3][2] += a.w * b.z; c[3][3] += a.w * b.w;
        }
    }

    float4 bb = *reinterpret_cast<const float4*>(&bih[j0 + (tx << 2)]);
#pragma unroll
    for (int i = 0; i < 4; i++) {
        float4 o = make_float4(c[i][0] + bb.x, c[i][1] + bb.y,
                               c[i][2] + bb.z, c[i][3] + bb.w);
        *reinterpret_cast<float4*>(
            &g_gi[(size_t)(row0 + (ty << 2) + i) * G3 + j0 + (tx << 2)]) = o;
    }
}

// ---------------------------------------------------------------------------
// K3: persistent recurrence. 128 CTAs x 2 adjacent batch rows, 256 threads =
// one hidden unit each. W all fp16: chunks 0..33 from smem, 34..63 from L2
// (both as uint2 = half2 x2; cvts issue in the FFMA rt=2 gaps). h double-
// buffered in smem (ONE barrier/step). gi[t] prefetched before the matvec.
// ---------------------------------------------------------------------------
__device__ __forceinline__ float fast_sigm(float v) {
    return __fdividef(1.0f, 1.0f + __expf(-v));
}
__device__ __forceinline__ float fast_tanh(float v) {
    float e = __expf(2.0f * v);
    return __fdividef(e - 1.0f, e + 1.0f);
}

__global__ void __launch_bounds__(256) gru_rec_kernel(
    const int* __restrict__ lengths, const float* __restrict__ bhh)
{
    extern __shared__ __align__(16) char dsm[];
    float2* hbuf = reinterpret_cast<float2*>(dsm);            // [2][256] float2
    uint2*  ws   = reinterpret_cast<uint2*>(dsm + 4096);      // [3][KQ_SMEM][256]

    int pair = blockIdx.x;              // 0..127
    int bA = pair * 2, bB = pair * 2 + 1;
    int lenA = lengths[bA], lenB = lengths[bB];
    int lmax = max(lenA, lenB);
    int tid  = threadIdx.x;

    // Cooperative load of the fp16 smem-resident W slice (chunks 0..KQ_SMEM-1)
    for (int i = tid; i < 3 * KQ_SMEM * 256; i += 256) {
        int g  = i / (KQ_SMEM * 256);
        int r  = i - g * (KQ_SMEM * 256);
        int kq = r >> 8;
        int ii = r & 255;
        ws[i] = g_wph[(g * 64 + kq) * 256 + ii];
    }
    hbuf[tid]       = make_float2(0.f, 0.f);
    hbuf[256 + tid] = make_float2(0.f, 0.f);

    float bhr = bhh[tid], bhz = bhh[256 + tid], bhn = bhh[512 + tid];
    const float* giA = g_gi + (size_t)bA * G3 + tid;
    const float* giB = g_gi + (size_t)bB * G3 + tid;
    __syncthreads();

    int p = 0;
    for (int t = 0; t < lmax; t++) {
        // ---- prefetch gi[t] (latency hides under the matvec) ----
        size_t toff = (size_t)t * (B_DIM * G3);
        bool actA = t < lenA, actB = t < lenB;
        float irA = 0.f, izA = 0.f, inA = 0.f;
        float irB = 0.f, izB = 0.f, inB = 0.f;
        if (actA) { irA = giA[toff]; izA = giA[toff + 256]; inA = giA[toff + 512]; }
        if (actB) { irB = giB[toff]; izB = giB[toff + 256]; inB = giB[toff + 512]; }

        float ar0 = 0.f, az0 = 0.f, an0 = 0.f;
        float ar1 = 0.f, az1 = 0.f, an1 = 0.f;
        const float4* hp = reinterpret_cast<const float4*>(hbuf + 256 * p);

        // ---- smem-resident fp16 W chunks ----
#pragma unroll 2
        for (int kq = 0; kq < KQ_SMEM; kq++) {
            float4 p01 = hp[2 * kq];
            float4 p23 = hp[2 * kq + 1];
            uint2 ur = ws[(0 * KQ_SMEM + kq) * 256 + tid];
            uint2 uz = ws[(1 * KQ_SMEM + kq) * 256 + tid];
            uint2 un = ws[(2 * KQ_SMEM + kq) * 256 + tid];
            float2 rlo = __half22float2(*reinterpret_cast<__half2*>(&ur.x));
            float2 rhi = __half22float2(*reinterpret_cast<__half2*>(&ur.y));
            float2 zlo = __half22float2(*reinterpret_cast<__half2*>(&uz.x));
            float2 zhi = __half22float2(*reinterpret_cast<__half2*>(&uz.y));
            float2 nlo = __half22float2(*reinterpret_cast<__half2*>(&un.x));
            float2 nhi = __half22float2(*reinterpret_cast<__half2*>(&un.y));
            ar0 += rlo.x * p01.x + rlo.y * p01.z + rhi.x * p23.x + rhi.y * p23.z;
            az0 += zlo.x * p01.x + zlo.y * p01.z + zhi.x * p23.x + zhi.y * p23.z;
            an0 += nlo.x * p01.x + nlo.y * p01.z + nhi.x * p23.x + nhi.y * p23.z;
            ar1 += rlo.x * p01.y + rlo.y * p01.w + rhi.x * p23.y + rhi.y * p23.w;
            az1 += zlo.x * p01.y + zlo.y * p01.w + zhi.x * p23.y + zhi.y * p23.w;
            an1 += nlo.x * p01.y + nlo.y * p01.w + nhi.x * p23.y + nhi.y * p23.w;
        }
        // ---- L2-streamed fp16 W chunks ----
#pragma unroll 2
        for (int kq = KQ_SMEM; kq < 64; kq++) {
            float4 p01 = hp[2 * kq];
            float4 p23 = hp[2 * kq + 1];
            uint2 ur = g_wph[(0 * 64 + kq) * 256 + tid];
            uint2 uz = g_wph[(1 * 64 + kq) * 256 + tid];
            uint2 un = g_wph[(2 * 64 + kq) * 256 + tid];
            float2 rlo = __half22float2(*reinterpret_cast<__half2*>(&ur.x));
            float2 rhi = __half22float2(*reinterpret_cast<__half2*>(&ur.y));
            float2 zlo = __half22float2(*reinterpret_cast<__half2*>(&uz.x));
            float2 zhi = __half22float2(*reinterpret_cast<__half2*>(&uz.y));
            float2 nlo = __half22float2(*reinterpret_cast<__half2*>(&un.x));
            float2 nhi = __half22float2(*reinterpret_cast<__half2*>(&un.y));
            ar0 += rlo.x * p01.x + rlo.y * p01.z + rhi.x * p23.x + rhi.y * p23.z;
            az0 += zlo.x * p01.x + zlo.y * p01.z + zhi.x * p23.x + zhi.y * p23.z;
            an0 += nlo.x * p01.x + nlo.y * p01.z + nhi.x * p23.x + nhi.y * p23.z;
            ar1 += rlo.x * p01.y + rlo.y * p01.w + rhi.x * p23.y + rhi.y * p23.w;
            az1 += zlo.x * p01.y + zlo.y * p01.w + zhi.x * p23.y + zhi.y * p23.w;
            an1 += nlo.x * p01.y + nlo.y * p01.w + nhi.x * p23.y + nhi.y * p23.w;
        }

        float2 hold = hbuf[256 * p + tid];
        float hA = hold.x, hB = hold.y;

        if (actA) {
            float r = fast_sigm(irA + ar0 + bhr);
            float z = fast_sigm(izA + az0 + bhz);
            float n = fast_tanh(inA + r * (an0 + bhn));
            hA = (1.f - z) * n + z * hA;
        }
        if (actB) {
            float r = fast_sigm(irB + ar1 + bhr);
            float z = fast_sigm(izB + az1 + bhz);
            float n = fast_tanh(inB + r * (an1 + bhn));
            hB = (1.f - z) * n + z * hB;
        }

        hbuf[256 * (p ^ 1) + tid] = make_float2(hA, hB);
        __syncthreads();                 // single barrier: publish h(t+1)
        p ^= 1;
    }

    float2 hf = hbuf[256 * p + tid];
    g_hfin[bA * 256 + tid] = hf.x;
    g_hfin[bB * 256 + tid] = hf.y;
}

// ---------------------------------------------------------------------------
// K4: out[i, :] = h_final[unsorted_indices[i], :]   (output is [1, B, H] fp32)
// ---------------------------------------------------------------------------
__global__ void __launch_bounds__(256) gather_kernel(
    const int* __restrict__ u, float* __restrict__ out)
{
    int b = blockIdx.x;
    out[b * 256 + threadIdx.x] = g_hfin[(size_t)u[b] * 256 + threadIdx.x];
}

// ---------------------------------------------------------------------------
// Launch. Inputs (metadata order): x, W_ih, W_hh, b_ih, b_hh, lengths,
// unsorted_indices. All launches graph-capturable; no sync, no alloc.
// ---------------------------------------------------------------------------
extern "C" void kernel_launch(void* const* d_in, const int* in_sizes, int n_in,
                              void* d_out, int out_size)
{
    const float* x       = (const float*)d_in[0];
    const float* wih     = (const float*)d_in[1];
    const float* whh     = (const float*)d_in[2];
    const float* bih     = (const float*)d_in[3];
    const float* bhh     = (const float*)d_in[4];
    const int*   lengths = (const int*)d_in[5];
    const int*   uns     = (const int*)d_in[6];
    float* out = (float*)d_out;

    static int smem_set = 0;
    if (!smem_set) {
        cudaFuncSetAttribute(gru_rec_kernel,
                             cudaFuncAttributeMaxDynamicSharedMemorySize,
                             SMEM_REC);
        smem_set = 1;
    }

    pack_whh_kernel<<<192, 256>>>(whh);

    dim3 g2(G3 / 64, (T_DIM * B_DIM) / 64);   // (12, 2048)
    gi_gemm_kernel<<<g2, 256>>>(x, wih, bih, lengths);

    gru_rec_kernel<<<B_DIM / 2, 256, SMEM_REC>>>(lengths, bhh);

    gather_kernel<<<B_DIM, 256>>>(uns, out);
}

// round 15
// speedup vs baseline: 2.1629x; 1.8438x over previous
#include <cuda_runtime.h>
#include <cuda_fp16.h>
#include <math.h>

// Problem constants
#define T_DIM 512
#define B_DIM 256
#define E_DIM 256
#define H_DIM 256
#define G3    768   // 3*H

// Recurrence W: fp16, packed [gate][kq][unit] (kq = group of 4 k-values).
// Chunks 0..KQS-1 cached in shared memory; chunks KQS..63 streamed from L2
// with a one-segment register lookahead. Segment = 4 chunks = 16 k values.
#define KQS 36
// smem: h fp16 double-buffered (2 rows x 2 phases x 256 half = 2KB) + W cache
#define SMEM_REC (2048 + 3 * KQS * 256 * 8)   // 223232

// ---------------------------------------------------------------------------
// Scratch (static __device__ globals — the sanctioned no-alloc workaround)
// ---------------------------------------------------------------------------
__device__ float g_gi[(size_t)T_DIM * B_DIM * G3];   // gi[t][b][3H], ~403 MB
__device__ uint2 g_wph[3 * 64 * 256];                // fp16 W_hh: half2 x2 per 4 k
__device__ float g_hfin[B_DIM * H_DIM];              // final hidden states

// ---------------------------------------------------------------------------
// K1: pack/transpose W_hh to fp16: g_wph[(g*64+kq)*256+i] =
//   {h2(W[g*256+i][4kq], W[..][4kq+1]), h2(W[..][4kq+2], W[..][4kq+3])}
// ---------------------------------------------------------------------------
__global__ void __launch_bounds__(256) pack_whh_kernel(const float* __restrict__ whh) {
    int idx = blockIdx.x * 256 + threadIdx.x;   // 0 .. 49151
    int i   = idx & 255;
    int gkq = idx >> 8;
    int g   = gkq >> 6;
    int kq  = gkq & 63;
    const float* src = whh + ((size_t)(g * 256 + i)) * 256 + 4 * kq;
    __half2 h01 = __floats2half2_rn(src[0], src[1]);
    __half2 h23 = __floats2half2_rn(src[2], src[3]);
    uint2 u;
    u.x = *reinterpret_cast<unsigned*>(&h01);
    u.y = *reinterpret_cast<unsigned*>(&h23);
    g_wph[idx] = u;
}

// ---------------------------------------------------------------------------
// K2: gi = x @ W_ih^T + b_ih. 64x64 tile, BK=16, 256 threads, 4x4 micro-tile,
// prefetched k-chunks. Inactive 64-row tiles skipped.
// ---------------------------------------------------------------------------
__global__ void __launch_bounds__(256) gi_gemm_kernel(
    const float* __restrict__ x, const float* __restrict__ wih,
    const float* __restrict__ bih, const int* __restrict__ lengths)
{
    __shared__ __align__(16) float As[16][64];
    __shared__ __align__(16) float Bs[16][64];
    __shared__ int s_nact;

    int tileN = blockIdx.x;
    int row0  = blockIdx.y << 6;
    int t     = row0 >> 8;
    int b0    = row0 & 255;

    if (threadIdx.x == 0) {
        int lo = 0, hi = B_DIM;
        while (lo < hi) {
            int mid = (lo + hi) >> 1;
            if (lengths[mid] > t) lo = mid + 1; else hi = mid;
        }
        s_nact = lo;
    }
    __syncthreads();
    if (b0 >= s_nact) return;

    int tid = threadIdx.x;
    int tx  = tid & 15;
    int ty  = tid >> 4;

    float c[4][4];
#pragma unroll
    for (int i = 0; i < 4; i++)
#pragma unroll
        for (int j = 0; j < 4; j++) c[i][j] = 0.f;

    int j0 = tileN << 6;
    int lr = tid >> 2;
    int lk = (tid & 3) << 2;
    const float* Ag = x   + (size_t)(row0 + lr) * 256 + lk;
    const float* Bg = wih + (size_t)(j0   + lr) * 256 + lk;

    float4 av = *reinterpret_cast<const float4*>(Ag);
    float4 bv = *reinterpret_cast<const float4*>(Bg);

    for (int kk = 0; kk < 256; kk += 16) {
        __syncthreads();
        As[lk + 0][lr] = av.x; As[lk + 1][lr] = av.y;
        As[lk + 2][lr] = av.z; As[lk + 3][lr] = av.w;
        Bs[lk + 0][lr] = bv.x; Bs[lk + 1][lr] = bv.y;
        Bs[lk + 2][lr] = bv.z; Bs[lk + 3][lr] = bv.w;
        __syncthreads();
        if (kk + 16 < 256) {
            av = *reinterpret_cast<const float4*>(Ag + kk + 16);
            bv = *reinterpret_cast<const float4*>(Bg + kk + 16);
        }
#pragma unroll
        for (int k = 0; k < 16; k++) {
            float4 a = *reinterpret_cast<const float4*>(&As[k][ty << 2]);
            float4 b = *reinterpret_cast<const float4*>(&Bs[k][tx << 2]);
            c[0][0] += a.x * b.x; c[0][1] += a.x * b.y; c[0][2] += a.x * b.z; c[0][3] += a.x * b.w;
            c[1][0] += a.y * b.x; c[1][1] += a.y * b.y; c[1][2] += a.y * b.z; c[1][3] += a.y * b.w;
            c[2][0] += a.z * b.x; c[2][1] += a.z * b.y; c[2][2] += a.z * b.z; c[2][3] += a.z * b.w;
            c[3][0] += a.w * b.x; c[3][1] += a.w * b.y; c[3][2] += a.w * b.z; c[3][3] += a.w * b.w;
        }
    }

    float4 bb = *reinterpret_cast<const float4*>(&bih[j0 + (tx << 2)]);
#pragma unroll
    for (int i = 0; i < 4; i++) {
        float4 o = make_float4(c[i][0] + bb.x, c[i][1] + bb.y,
                               c[i][2] + bb.z, c[i][3] + bb.w);
        *reinterpret_cast<float4*>(
            &g_gi[(size_t)(row0 + (ty << 2) + i) * G3 + j0 + (tx << 2)]) = o;
    }
}

// ---------------------------------------------------------------------------
// K3: persistent recurrence, HFMA2 inner loop.
// 128 CTAs x 2 adjacent batch rows, 256 threads = one hidden unit each.
// h stored fp16 in smem (double-buffered). Per chunk (4 k, 3 gates, 2 rows):
// 12 HFMA2, zero cvts. half2 accumulators folded to fp32 every 4 chunks.
// ---------------------------------------------------------------------------
__device__ __forceinline__ float fast_sigm(float v) {
    return __fdividef(1.0f, 1.0f + __expf(-v));
}
__device__ __forceinline__ float fast_tanh(float v) {
    float e = __expf(2.0f * v);
    return __fdividef(e - 1.0f, e + 1.0f);
}

#define CHUNK(ur, uz, un, kq) do {                                          \
    uint2 hau = *reinterpret_cast<const uint2*>(hAp + 4 * (kq));            \
    uint2 hbu = *reinterpret_cast<const uint2*>(hBp + 4 * (kq));            \
    __half2 ha01 = *reinterpret_cast<const __half2*>(&hau.x);               \
    __half2 ha23 = *reinterpret_cast<const __half2*>(&hau.y);               \
    __half2 hb01 = *reinterpret_cast<const __half2*>(&hbu.x);               \
    __half2 hb23 = *reinterpret_cast<const __half2*>(&hbu.y);               \
    __half2 wr01 = *reinterpret_cast<const __half2*>(&(ur).x);              \
    __half2 wr23 = *reinterpret_cast<const __half2*>(&(ur).y);              \
    __half2 wz01 = *reinterpret_cast<const __half2*>(&(uz).x);              \
    __half2 wz23 = *reinterpret_cast<const __half2*>(&(uz).y);              \
    __half2 wn01 = *reinterpret_cast<const __half2*>(&(un).x);              \
    __half2 wn23 = *reinterpret_cast<const __half2*>(&(un).y);              \
    cAr = __hfma2(wr01, ha01, cAr); cAr = __hfma2(wr23, ha23, cAr);         \
    cAz = __hfma2(wz01, ha01, cAz); cAz = __hfma2(wz23, ha23, cAz);         \
    cAn = __hfma2(wn01, ha01, cAn); cAn = __hfma2(wn23, ha23, cAn);         \
    cBr = __hfma2(wr01, hb01, cBr); cBr = __hfma2(wr23, hb23, cBr);         \
    cBz = __hfma2(wz01, hb01, cBz); cBz = __hfma2(wz23, hb23, cBz);         \
    cBn = __hfma2(wn01, hb01, cBn); cBn = __hfma2(wn23, hb23, cBn);         \
} while (0)

#define FOLD() do { float2 f_;                                              \
    f_ = __half22float2(cAr); ar0 += f_.x + f_.y; cAr = hz2;                \
    f_ = __half22float2(cAz); az0 += f_.x + f_.y; cAz = hz2;                \
    f_ = __half22float2(cAn); an0 += f_.x + f_.y; cAn = hz2;                \
    f_ = __half22float2(cBr); ar1 += f_.x + f_.y; cBr = hz2;                \
    f_ = __half22float2(cBz); az1 += f_.x + f_.y; cBz = hz2;                \
    f_ = __half22float2(cBn); an1 += f_.x + f_.y; cBn = hz2;                \
} while (0)

__global__ void __launch_bounds__(256) gru_rec_kernel(
    const int* __restrict__ lengths, const float* __restrict__ bhh)
{
    extern __shared__ __align__(16) char dsm[];
    __half* hbA = reinterpret_cast<__half*>(dsm);           // [2][256]
    __half* hbB = reinterpret_cast<__half*>(dsm + 1024);    // [2][256]
    uint2*  ws  = reinterpret_cast<uint2*>(dsm + 2048);     // [3][KQS][256]

    int pair = blockIdx.x;
    int bA = pair * 2, bB = pair * 2 + 1;
    int lenA = lengths[bA], lenB = lengths[bB];
    int lmax = max(lenA, lenB);
    int tid  = threadIdx.x;

    // Cooperative load of the fp16 smem-resident W slice (chunks 0..KQS-1)
    for (int i = tid; i < 3 * KQS * 256; i += 256) {
        int g  = i / (KQS * 256);
        int r  = i - g * (KQS * 256);
        int kq = r >> 8;
        int ii = r & 255;
        ws[i] = g_wph[(g * 64 + kq) * 256 + ii];
    }
    hbA[tid] = __float2half(0.f); hbA[256 + tid] = __float2half(0.f);
    hbB[tid] = __float2half(0.f); hbB[256 + tid] = __float2half(0.f);

    float bhr = bhh[tid], bhz = bhh[256 + tid], bhn = bhh[512 + tid];
    const float* giA = g_gi + (size_t)bA * G3 + tid;
    const float* giB = g_gi + (size_t)bB * G3 + tid;
    float hAf = 0.f, hBf = 0.f;          // fp32 master hidden state (this unit)
    const __half2 hz2 = __float2half2_rn(0.f);
    __syncthreads();

    int p = 0;
    for (int t = 0; t < lmax; t++) {
        // ---- prefetch gi[t] (latency hides under the matvec) ----
        size_t toff = (size_t)t * (B_DIM * G3);
        bool actA = t < lenA, actB = t < lenB;
        float irA = 0.f, izA = 0.f, inA = 0.f;
        float irB = 0.f, izB = 0.f, inB = 0.f;
        if (actA) { irA = giA[toff]; izA = giA[toff + 256]; inA = giA[toff + 512]; }
        if (actB) { irB = giB[toff]; izB = giB[toff + 256]; inB = giB[toff + 512]; }

        const __half* hAp = hbA + 256 * p;
        const __half* hBp = hbB + 256 * p;
        float ar0 = 0.f, az0 = 0.f, an0 = 0.f;
        float ar1 = 0.f, az1 = 0.f, an1 = 0.f;
        __half2 cAr = hz2, cAz = hz2, cAn = hz2;
        __half2 cBr = hz2, cBz = hz2, cBn = hz2;

        // ---- smem-resident segments (chunks 0..KQS-1) ----
        for (int s = 0; s < KQS / 4; s++) {
#pragma unroll
            for (int j = 0; j < 4; j++) {
                int kq = s * 4 + j;
                uint2 ur = ws[(0 * KQS + kq) * 256 + tid];
                uint2 uz = ws[(1 * KQS + kq) * 256 + tid];
                uint2 un = ws[(2 * KQS + kq) * 256 + tid];
                CHUNK(ur, uz, un, kq);
            }
            FOLD();
        }

        // ---- L2-streamed segments (chunks KQS..63), 1-segment lookahead ----
        uint2 wb0[12], wb1[12];
#pragma unroll
        for (int j = 0; j < 4; j++) {
            int kq = KQS + j;
            wb0[3 * j + 0] = g_wph[(0 * 64 + kq) * 256 + tid];
            wb0[3 * j + 1] = g_wph[(1 * 64 + kq) * 256 + tid];
            wb0[3 * j + 2] = g_wph[(2 * 64 + kq) * 256 + tid];
        }
        for (int s = KQS / 4; s < 16; s++) {
            if (s < 15) {
#pragma unroll
                for (int j = 0; j < 4; j++) {
                    int kq = (s + 1) * 4 + j;
                    wb1[3 * j + 0] = g_wph[(0 * 64 + kq) * 256 + tid];
                    wb1[3 * j + 1] = g_wph[(1 * 64 + kq) * 256 + tid];
                    wb1[3 * j + 2] = g_wph[(2 * 64 + kq) * 256 + tid];
                }
            }
#pragma unroll
            for (int j = 0; j < 4; j++)
                CHUNK(wb0[3 * j], wb0[3 * j + 1], wb0[3 * j + 2], s * 4 + j);
            FOLD();
#pragma unroll
            for (int i = 0; i < 12; i++) wb0[i] = wb1[i];
        }

        // ---- pointwise + freeze semantics ----
        if (actA) {
            float r = fast_sigm(irA + ar0 + bhr);
            float z = fast_sigm(izA + az0 + bhz);
            float n = fast_tanh(inA + r * (an0 + bhn));
            hAf = (1.f - z) * n + z * hAf;
        }
        if (actB) {
            float r = fast_sigm(irB + ar1 + bhr);
            float z = fast_sigm(izB + az1 + bhz);
            float n = fast_tanh(inB + r * (an1 + bhn));
            hBf = (1.f - z) * n + z * hBf;
        }

        hbA[256 * (p ^ 1) + tid] = __float2half(hAf);
        hbB[256 * (p ^ 1) + tid] = __float2half(hBf);
        __syncthreads();                 // single barrier: publish h(t+1)
        p ^= 1;
    }

    g_hfin[bA * 256 + tid] = hAf;
    g_hfin[bB * 256 + tid] = hBf;
}

// ---------------------------------------------------------------------------
// K4: out[i, :] = h_final[unsorted_indices[i], :]
// ---------------------------------------------------------------------------
__global__ void __launch_bounds__(256) gather_kernel(
    const int* __restrict__ u, float* __restrict__ out)
{
    int b = blockIdx.x;
    out[b * 256 + threadIdx.x] = g_hfin[(size_t)u[b] * 256 + threadIdx.x];
}

// ---------------------------------------------------------------------------
// Launch. Inputs: x, W_ih, W_hh, b_ih, b_hh, lengths, unsorted_indices.
// ---------------------------------------------------------------------------
extern "C" void kernel_launch(void* const* d_in, const int* in_sizes, int n_in,
                              void* d_out, int out_size)
{
    const float* x       = (const float*)d_in[0];
    const float* wih     = (const float*)d_in[1];
    const float* whh     = (const float*)d_in[2];
    const float* bih     = (const float*)d_in[3];
    const float* bhh     = (const float*)d_in[4];
    const int*   lengths = (const int*)d_in[5];
    const int*   uns     = (const int*)d_in[6];
    float* out = (float*)d_out;

    static int smem_set = 0;
    if (!smem_set) {
        cudaFuncSetAttribute(gru_rec_kernel,
                             cudaFuncAttributeMaxDynamicSharedMemorySize,
                             SMEM_REC);
        smem_set = 1;
    }

    pack_whh_kernel<<<192, 256>>>(whh);

    dim3 g2(G3 / 64, (T_DIM * B_DIM) / 64);   // (12, 2048)
    gi_gemm_kernel<<<g2, 256>>>(x, wih, bih, lengths);

    gru_rec_kernel<<<B_DIM / 2, 256, SMEM_REC>>>(lengths, bhh);

    gather_kernel<<<B_DIM, 256>>>(uns, out);
}